// round 5
// baseline (speedup 1.0000x reference)
#include <cuda_runtime.h>
#include <math.h>
#include <stdint.h>

// Problem constants (fixed by setup_inputs)
#define S0   2048
#define S1   256
#define ST   2304          // S0 + S1
#define NH   24            // heads
#define HD   64            // dim_head
#define DIM  1536          // model dim == NH*HD
#define NQKV 4608          // 3*NH*HD

// ---------------- scratch (static device globals; no allocation) -----------
__device__ float g_qkv[ST * NQKV];        // (s, 3*H*D) packed both modalities
__device__ float g_Q[NH * ST * HD];       // (h, s, d)
__device__ float g_K[NH * ST * HD];
__device__ float g_V[NH * ST * HD];
__device__ float g_attn[ST * DIM];        // (s, h*d) attention output

// ---------------------------------------------------------------------------
// tf32 helpers (shared fragment conventions for all MMA kernels)
// ---------------------------------------------------------------------------
__device__ __forceinline__ uint32_t f32_to_tf32(float x) {
    uint32_t u;
    asm("cvt.rna.tf32.f32 %0, %1;" : "=r"(u) : "f"(x));
    return u;
}

// split x = hi + lo with hi = tf32(x); the subtraction is exact.
__device__ __forceinline__ void tf32_split(float x, uint32_t& hi, uint32_t& lo) {
    hi = f32_to_tf32(x);
    lo = f32_to_tf32(x - __uint_as_float(hi));
}

__device__ __forceinline__ void mma_tf32(float c[4], const uint32_t a[4],
                                         const uint32_t b[2]) {
    asm volatile(
        "mma.sync.aligned.m16n8k8.row.col.f32.tf32.tf32.f32 "
        "{%0,%1,%2,%3}, {%4,%5,%6,%7}, {%8,%9}, {%0,%1,%2,%3};"
        : "+f"(c[0]), "+f"(c[1]), "+f"(c[2]), "+f"(c[3])
        : "r"(a[0]), "r"(a[1]), "r"(a[2]), "r"(a[3]), "r"(b[0]), "r"(b[1]));
}

// ---------------------------------------------------------------------------
// 3xTF32 tensor-core GEMM, dual-segment (two modalities in one launch):
//   rows [0, M0)        : C0 = A0 * B0
//   rows [M0, M0+M1)    : C1 = A1 * B1
// All matrices row-major fp32; same N, K for both segments.
// hi/lo split; hi*hi + hi*lo + lo*hi -> ~2^-22 relative accuracy.
//
// Block tile 128x128, BK=16, 256 threads = 8 warps (4m x 2n), warp = m32 x n64.
// Double-buffered dynamic SMEM, pitch 136 (8 mod 32) -> conflict-free
// fragment loads (8*ca + ra + const covers all 32 banks).
// Requires M0%128==0, M1%128==0, N%128==0, K%16==0.
// ---------------------------------------------------------------------------
#define GP 136                            // SMEM pitch (u32 units)
#define GEMM_TILE_U32 (16 * GP)           // one [16][136] tile
#define GEMM_SMEM_BYTES (8 * GEMM_TILE_U32 * 4)   // 2 buf x {Ah,Al,Bh,Bl}

extern __shared__ uint32_t gsm[];

__global__ __launch_bounds__(256, 2) void gemm_tf32x3_dual_kernel(
    const float* __restrict__ A0, const float* __restrict__ B0, float* __restrict__ C0,
    const float* __restrict__ A1, const float* __restrict__ B1, float* __restrict__ C1,
    int M0, int N, int K)
{
    // smem layout: [buf][{Ah,Al,Bh,Bl}][16][GP]
    uint32_t* Ah[2]; uint32_t* Al[2]; uint32_t* Bh[2]; uint32_t* Bl[2];
    #pragma unroll
    for (int b = 0; b < 2; b++) {
        Ah[b] = gsm + (b * 4 + 0) * GEMM_TILE_U32;
        Al[b] = gsm + (b * 4 + 1) * GEMM_TILE_U32;
        Bh[b] = gsm + (b * 4 + 2) * GEMM_TILE_U32;
        Bl[b] = gsm + (b * 4 + 3) * GEMM_TILE_U32;
    }

    const int tid  = threadIdx.x;
    const int warp = tid >> 5;
    const int lane = tid & 31;
    const int wm   = warp >> 1;       // 0..3  (m32 slab)
    const int wn   = warp & 1;        // 0..1  (n64 slab)

    // segment select
    const int my = blockIdx.y * 128;
    const float* A; const float* B; float* C;
    int m0;
    if (my < M0) { A = A0; B = B0; C = C0; m0 = my; }
    else         { A = A1; B = B1; C = C1; m0 = my - M0; }
    const int n0 = blockIdx.x * 128;

    const int ra = lane >> 2;         // 0..7
    const int ca = lane & 3;          // 0..3

    // global load mapping (two 256-thread passes cover the tile)
    // A: 128 rows x 16 cols ; B: 16 rows x 128 cols
    const int arow0 = tid >> 2;               // 0..63  (pass i adds 64)
    const int acol  = (tid & 3) << 2;         // 0,4,8,12
    const int brow0 = tid >> 5;               // 0..7   (pass i adds 8)
    const int bcol  = (tid & 31) << 2;        // 0..124

    const float* Aptr = A + (size_t)(m0 + arow0) * K + acol;
    const float* Bptr = B + (size_t)brow0 * N + n0 + bcol;

    float acc[2][8][4];
    #pragma unroll
    for (int i = 0; i < 2; i++)
        #pragma unroll
        for (int j = 0; j < 8; j++)
            #pragma unroll
            for (int r = 0; r < 4; r++)
                acc[i][j][r] = 0.0f;

    float4 avr[2], bvr[2];

    // ---- prologue: load tile 0 ----
    #pragma unroll
    for (int i = 0; i < 2; i++) {
        avr[i] = *(const float4*)(Aptr + (size_t)i * 64 * K);
        bvr[i] = *(const float4*)(Bptr + (size_t)i * 8 * N);
    }
    // split + store buf 0
    #pragma unroll
    for (int i = 0; i < 2; i++) {
        const int arow = arow0 + i * 64;
        float af[4] = {avr[i].x, avr[i].y, avr[i].z, avr[i].w};
        #pragma unroll
        for (int j = 0; j < 4; j++)
            tf32_split(af[j], Ah[0][(acol + j) * GP + arow], Al[0][(acol + j) * GP + arow]);
        const int brow = brow0 + i * 8;
        float bf[4] = {bvr[i].x, bvr[i].y, bvr[i].z, bvr[i].w};
        uint4 hv, lv;
        tf32_split(bf[0], hv.x, lv.x);
        tf32_split(bf[1], hv.y, lv.y);
        tf32_split(bf[2], hv.z, lv.z);
        tf32_split(bf[3], hv.w, lv.w);
        *(uint4*)&Bh[0][brow * GP + bcol] = hv;
        *(uint4*)&Bl[0][brow * GP + bcol] = lv;
    }
    __syncthreads();

    const int ntiles = K >> 4;
    for (int kt = 0; kt < ntiles; kt++) {
        const int cur = kt & 1;
        const int nxt = cur ^ 1;

        // ---- prefetch next tile into registers ----
        if (kt + 1 < ntiles) {
            #pragma unroll
            for (int i = 0; i < 2; i++) {
                avr[i] = *(const float4*)(Aptr + (size_t)i * 64 * K + (kt + 1) * 16);
                bvr[i] = *(const float4*)(Bptr + (size_t)((kt + 1) * 16 + i * 8) * N);
            }
        }

        // ---- compute on current buffer: 2 k-steps of 8 ----
        #pragma unroll
        for (int ks = 0; ks < 2; ks++) {
            const int k4 = ks * 8;
            uint32_t ah[2][4], al[2][4], bh[8][2], bl[8][2];

            #pragma unroll
            for (int mt = 0; mt < 2; mt++) {
                int mrow = wm * 32 + mt * 16;
                ah[mt][0] = Ah[cur][(k4 + ca) * GP + mrow + ra];
                ah[mt][1] = Ah[cur][(k4 + ca) * GP + mrow + ra + 8];
                ah[mt][2] = Ah[cur][(k4 + ca + 4) * GP + mrow + ra];
                ah[mt][3] = Ah[cur][(k4 + ca + 4) * GP + mrow + ra + 8];
                al[mt][0] = Al[cur][(k4 + ca) * GP + mrow + ra];
                al[mt][1] = Al[cur][(k4 + ca) * GP + mrow + ra + 8];
                al[mt][2] = Al[cur][(k4 + ca + 4) * GP + mrow + ra];
                al[mt][3] = Al[cur][(k4 + ca + 4) * GP + mrow + ra + 8];
            }
            #pragma unroll
            for (int nt = 0; nt < 8; nt++) {
                int ncol = wn * 64 + nt * 8 + ra;
                bh[nt][0] = Bh[cur][(k4 + ca) * GP + ncol];
                bh[nt][1] = Bh[cur][(k4 + ca + 4) * GP + ncol];
                bl[nt][0] = Bl[cur][(k4 + ca) * GP + ncol];
                bl[nt][1] = Bl[cur][(k4 + ca + 4) * GP + ncol];
            }

            #pragma unroll
            for (int mt = 0; mt < 2; mt++)
                #pragma unroll
                for (int nt = 0; nt < 8; nt++) {
                    mma_tf32(acc[mt][nt], al[mt], bh[nt]);
                    mma_tf32(acc[mt][nt], ah[mt], bl[nt]);
                    mma_tf32(acc[mt][nt], ah[mt], bh[nt]);
                }
        }

        // ---- split + store prefetched tile into the other buffer ----
        if (kt + 1 < ntiles) {
            #pragma unroll
            for (int i = 0; i < 2; i++) {
                const int arow = arow0 + i * 64;
                float af[4] = {avr[i].x, avr[i].y, avr[i].z, avr[i].w};
                #pragma unroll
                for (int j = 0; j < 4; j++)
                    tf32_split(af[j], Ah[nxt][(acol + j) * GP + arow],
                                      Al[nxt][(acol + j) * GP + arow]);
                const int brow = brow0 + i * 8;
                float bf[4] = {bvr[i].x, bvr[i].y, bvr[i].z, bvr[i].w};
                uint4 hv, lv;
                tf32_split(bf[0], hv.x, lv.x);
                tf32_split(bf[1], hv.y, lv.y);
                tf32_split(bf[2], hv.z, lv.z);
                tf32_split(bf[3], hv.w, lv.w);
                *(uint4*)&Bh[nxt][brow * GP + bcol] = hv;
                *(uint4*)&Bl[nxt][brow * GP + bcol] = lv;
            }
            __syncthreads();
        }
    }

    // ---- epilogue ----
    #pragma unroll
    for (int mt = 0; mt < 2; mt++) {
        int gr = m0 + wm * 32 + mt * 16 + ra;
        #pragma unroll
        for (int nt = 0; nt < 8; nt++) {
            int gc = n0 + wn * 64 + nt * 8 + ca * 2;
            *(float2*)&C[(size_t)gr * N + gc] =
                make_float2(acc[mt][nt][0], acc[mt][nt][1]);
            *(float2*)&C[(size_t)(gr + 8) * N + gc] =
                make_float2(acc[mt][nt][2], acc[mt][nt][3]);
        }
    }
}

// ---------------------------------------------------------------------------
// QKV epilogue: per token s, for every head: RMSNorm(q,k) + RoPE(q,k), copy v.
// ---------------------------------------------------------------------------
__global__ __launch_bounds__(256) void qkv_epilogue_kernel(
    const float* __restrict__ gq0, const float* __restrict__ gk0,
    const float* __restrict__ gq1, const float* __restrict__ gk1)
{
    const int s = blockIdx.x;
    const int modality = (s < S0) ? 0 : 1;
    const int s_local  = modality ? (s - S0) : s;
    const float* gq = modality ? gq1 : gq0;
    const float* gk = modality ? gk1 : gk0;

    const int warp = threadIdx.x >> 5;
    const int lane = threadIdx.x & 31;

    float inv = __powf(10000.0f, -(float)lane / 32.0f);
    float ang = (float)s_local * inv;
    float c, sn;
    sincosf(ang, &sn, &c);

    const float* row = g_qkv + (size_t)s * NQKV;

    for (int h = warp; h < NH; h += 8) {
        {
            float x0 = row[0 * DIM + h * HD + lane];
            float x1 = row[0 * DIM + h * HD + lane + 32];
            float ss = x0 * x0 + x1 * x1;
            #pragma unroll
            for (int off = 16; off > 0; off >>= 1)
                ss += __shfl_xor_sync(0xffffffffu, ss, off);
            float r = rsqrtf(ss * (1.0f / 64.0f) + 1e-6f);
            float q0 = x0 * r * gq[lane];
            float q1 = x1 * r * gq[lane + 32];
            g_Q[((size_t)h * ST + s) * HD + lane]      = q0 * c - q1 * sn;
            g_Q[((size_t)h * ST + s) * HD + lane + 32] = q1 * c + q0 * sn;
        }
        {
            float x0 = row[1 * DIM + h * HD + lane];
            float x1 = row[1 * DIM + h * HD + lane + 32];
            float ss = x0 * x0 + x1 * x1;
            #pragma unroll
            for (int off = 16; off > 0; off >>= 1)
                ss += __shfl_xor_sync(0xffffffffu, ss, off);
            float r = rsqrtf(ss * (1.0f / 64.0f) + 1e-6f);
            float k0 = x0 * r * gk[lane];
            float k1 = x1 * r * gk[lane + 32];
            g_K[((size_t)h * ST + s) * HD + lane]      = k0 * c - k1 * sn;
            g_K[((size_t)h * ST + s) * HD + lane + 32] = k1 * c + k0 * sn;
        }
        g_V[((size_t)h * ST + s) * HD + lane]      = row[2 * DIM + h * HD + lane];
        g_V[((size_t)h * ST + s) * HD + lane + 32] = row[2 * DIM + h * HD + lane + 32];
    }
}

// ---------------------------------------------------------------------------
// Tensor-core attention: softmax(Q K^T / 8) V per head, 3xTF32 everywhere.
// Block = 128 queries x one head, 256 threads = 8 warps; warp owns m16 rows.
// Key loop in tiles of 64. No online max (|score| <= 8 by RMS-norm bound).
// P converted C-layout -> A-layout by warp shuffles (no SMEM round-trip).
// SMEM arrays row-major, pitch 72 floats.
// ---------------------------------------------------------------------------
#define AQ_BQ   128
#define AQ_BK   64
#define AQ_P    72                       // pitch in floats

extern __shared__ float attn_smem[];     // Qs[128][72] | Ks[64][72] | Vs[64][72]

__global__ __launch_bounds__(256) void attn_mma_kernel()
{
    float* Qs = attn_smem;               // [128][AQ_P]
    float* Ks = Qs + AQ_BQ * AQ_P;       // [64][AQ_P]
    float* Vs = Ks + AQ_BK * AQ_P;       // [64][AQ_P]

    const int tid  = threadIdx.x;
    const int warp = tid >> 5;           // 0..7 -> query rows [warp*16, +16)
    const int lane = tid & 31;
    const int ra   = lane >> 2;          // 0..7
    const int ca   = lane & 3;           // 0..3
    const int h    = blockIdx.y;
    const int qb   = blockIdx.x * AQ_BQ;

    // ---- stage Q slab (x 1/8 softmax scale), row-major [q][d] ----
    const float* Qg = g_Q + ((size_t)h * ST + qb) * HD;
    #pragma unroll
    for (int i = 0; i < 8; i++) {
        int idx = tid + i * 256;         // 0..2047 float4 ids
        int q  = idx >> 4;
        int d4 = (idx & 15) << 2;
        float4 v = *(const float4*)&Qg[(size_t)q * HD + d4];
        v.x *= 0.125f; v.y *= 0.125f; v.z *= 0.125f; v.w *= 0.125f;
        *(float4*)&Qs[q * AQ_P + d4] = v;
    }

    float oacc[8][4];
    #pragma unroll
    for (int nt = 0; nt < 8; nt++)
        #pragma unroll
        for (int r = 0; r < 4; r++) oacc[nt][r] = 0.0f;
    float l0 = 0.0f, l1 = 0.0f;

    const int q0 = warp * 16;
    const int src1 = (lane & ~3) | (ca >> 1);   // shfl source A
    const int src2 = src1 + 2;                  // shfl source B
    const bool odd = ca & 1;

    for (int kt = 0; kt < ST / AQ_BK; kt++) {
        __syncthreads();   // previous iteration finished reading Ks/Vs
        const float* Kg = g_K + ((size_t)h * ST + kt * AQ_BK) * HD;
        const float* Vg = g_V + ((size_t)h * ST + kt * AQ_BK) * HD;
        #pragma unroll
        for (int i = 0; i < 4; i++) {
            int idx = tid + i * 256;     // 0..1023 float4 ids
            int r  = idx >> 4;
            int d4 = (idx & 15) << 2;
            *(float4*)&Ks[r * AQ_P + d4] = *(const float4*)&Kg[(size_t)r * HD + d4];
            *(float4*)&Vs[r * AQ_P + d4] = *(const float4*)&Vg[(size_t)r * HD + d4];
        }
        __syncthreads();

        // ---- scores: S[16 q][64 key] = Q . K^T  (reduce over d) ----
        float p[8][4];
        #pragma unroll
        for (int nt = 0; nt < 8; nt++)
            #pragma unroll
            for (int r = 0; r < 4; r++) p[nt][r] = 0.0f;

        #pragma unroll
        for (int kk = 0; kk < 8; kk++) {
            uint32_t ah[4], al[4];
            tf32_split(Qs[(q0 + ra)     * AQ_P + kk * 8 + ca],     ah[0], al[0]);
            tf32_split(Qs[(q0 + ra + 8) * AQ_P + kk * 8 + ca],     ah[1], al[1]);
            tf32_split(Qs[(q0 + ra)     * AQ_P + kk * 8 + ca + 4], ah[2], al[2]);
            tf32_split(Qs[(q0 + ra + 8) * AQ_P + kk * 8 + ca + 4], ah[3], al[3]);
            #pragma unroll
            for (int nt = 0; nt < 8; nt++) {
                uint32_t bh[2], bl[2];
                tf32_split(Ks[(nt * 8 + ra) * AQ_P + kk * 8 + ca],     bh[0], bl[0]);
                tf32_split(Ks[(nt * 8 + ra) * AQ_P + kk * 8 + ca + 4], bh[1], bl[1]);
                mma_tf32(p[nt], al, bh);
                mma_tf32(p[nt], ah, bl);
                mma_tf32(p[nt], ah, bh);
            }
        }

        // ---- softmax numerators + row-sum accumulation ----
        float rs0 = 0.0f, rs1 = 0.0f;
        #pragma unroll
        for (int nt = 0; nt < 8; nt++) {
            p[nt][0] = __expf(p[nt][0]);
            p[nt][1] = __expf(p[nt][1]);
            p[nt][2] = __expf(p[nt][2]);
            p[nt][3] = __expf(p[nt][3]);
            rs0 += p[nt][0] + p[nt][1];
            rs1 += p[nt][2] + p[nt][3];
        }
        rs0 += __shfl_xor_sync(0xffffffffu, rs0, 1);
        rs0 += __shfl_xor_sync(0xffffffffu, rs0, 2);
        rs1 += __shfl_xor_sync(0xffffffffu, rs1, 1);
        rs1 += __shfl_xor_sync(0xffffffffu, rs1, 2);
        l0 += rs0;
        l1 += rs1;

        // ---- O += P . V  (reduce over keys); P via shuffle to A-layout ----
        #pragma unroll
        for (int kk = 0; kk < 8; kk++) {
            float v0a = __shfl_sync(0xffffffffu, p[kk][0], src1);
            float v1a = __shfl_sync(0xffffffffu, p[kk][1], src1);
            float v2a = __shfl_sync(0xffffffffu, p[kk][2], src1);
            float v3a = __shfl_sync(0xffffffffu, p[kk][3], src1);
            float v0b = __shfl_sync(0xffffffffu, p[kk][0], src2);
            float v1b = __shfl_sync(0xffffffffu, p[kk][1], src2);
            float v2b = __shfl_sync(0xffffffffu, p[kk][2], src2);
            float v3b = __shfl_sync(0xffffffffu, p[kk][3], src2);
            uint32_t ah[4], al[4];
            tf32_split(odd ? v1a : v0a, ah[0], al[0]);   // (row ra,   col ca)
            tf32_split(odd ? v3a : v2a, ah[1], al[1]);   // (row ra+8, col ca)
            tf32_split(odd ? v1b : v0b, ah[2], al[2]);   // (row ra,   col ca+4)
            tf32_split(odd ? v3b : v2b, ah[3], al[3]);   // (row ra+8, col ca+4)
            #pragma unroll
            for (int nt = 0; nt < 8; nt++) {
                uint32_t bh[2], bl[2];
                tf32_split(Vs[(kk * 8 + ca)     * AQ_P + nt * 8 + ra], bh[0], bl[0]);
                tf32_split(Vs[(kk * 8 + ca + 4) * AQ_P + nt * 8 + ra], bh[1], bl[1]);
                mma_tf32(oacc[nt], al, bh);
                mma_tf32(oacc[nt], ah, bl);
                mma_tf32(oacc[nt], ah, bh);
            }
        }
    }

    // ---- epilogue: divide by row sums, write (s, h*d) layout ----
    const float il0 = 1.0f / l0;
    const float il1 = 1.0f / l1;
    const int gq0r = qb + q0 + ra;
    #pragma unroll
    for (int nt = 0; nt < 8; nt++) {
        int gc = h * HD + nt * 8 + ca * 2;
        *(float2*)&g_attn[(size_t)gq0r * DIM + gc] =
            make_float2(oacc[nt][0] * il0, oacc[nt][1] * il0);
        *(float2*)&g_attn[(size_t)(gq0r + 8) * DIM + gc] =
            make_float2(oacc[nt][2] * il1, oacc[nt][3] * il1);
    }
}

// ---------------------------------------------------------------------------
extern "C" void kernel_launch(void* const* d_in, const int* in_sizes, int n_in,
                              void* d_out, int out_size)
{
    const float* x0     = (const float*)d_in[0];
    const float* x1     = (const float*)d_in[1];
    const float* w_qkv0 = (const float*)d_in[2];
    const float* w_qkv1 = (const float*)d_in[3];
    const float* w_out0 = (const float*)d_in[4];
    const float* w_out1 = (const float*)d_in[5];
    const float* gq0    = (const float*)d_in[6];
    const float* gk0    = (const float*)d_in[7];
    const float* gq1    = (const float*)d_in[8];
    const float* gk1    = (const float*)d_in[9];
    float* out = (float*)d_out;

    float *qkv, *attn;
    cudaGetSymbolAddress((void**)&qkv,  g_qkv);
    cudaGetSymbolAddress((void**)&attn, g_attn);

    cudaFuncSetAttribute(gemm_tf32x3_dual_kernel,
                         cudaFuncAttributeMaxDynamicSharedMemorySize, GEMM_SMEM_BYTES);
    const int attn_smem_bytes = (AQ_BQ + 2 * AQ_BK) * AQ_P * sizeof(float); // 73728
    cudaFuncSetAttribute(attn_mma_kernel,
                         cudaFuncAttributeMaxDynamicSharedMemorySize, attn_smem_bytes);

    // 1) QKV projections, both modalities in one launch (grid.y spans S0+S1)
    gemm_tf32x3_dual_kernel<<<dim3(NQKV / 128, ST / 128), 256, GEMM_SMEM_BYTES>>>(
        x0, w_qkv0, qkv,
        x1, w_qkv1, qkv + (size_t)S0 * NQKV,
        S0, NQKV, DIM);

    // 2) rmsnorm + RoPE + scatter to (h,s,d)
    qkv_epilogue_kernel<<<ST, 256>>>(gq0, gk0, gq1, gk1);

    // 3) joint attention over packed sequence (tensor cores)
    attn_mma_kernel<<<dim3(ST / AQ_BQ, NH), 256, attn_smem_bytes>>>();

    // 4) output projections, both modalities in one launch
    gemm_tf32x3_dual_kernel<<<dim3(DIM / 128, ST / 128), 256, GEMM_SMEM_BYTES>>>(
        attn, w_out0, out,
        attn + (size_t)S0 * DIM, w_out1, out + (size_t)S0 * DIM,
        S0, DIM, DIM);
}